// round 1
// baseline (speedup 1.0000x reference)
#include <cuda_runtime.h>
#include <cuda_bf16.h>
#include <math.h>

// Problem constants
#define BB 8
#define NN 2048
#define FF 64
#define FH 64
#define HH 4

#define TI 64     // rows per CTA (kernel 2)
#define TJ 128    // cols per j-tile (kernel 2)

// -------- scratch (static device globals; no allocation) --------
__device__ float g_feats[BB * HH * NN * FH];  // [b][h][n][o], 16.8 MB
__device__ float g_ss[BB * HH * NN];          // s_self
__device__ float g_sn[BB * HH * NN];          // s_neigh

// ==================== Kernel 1: feats + logit dots ====================
// grid = B * N / 16 = 1024, block = 256. thread t -> (h = t>>6, o = t&63)
__global__ __launch_bounds__(256) void k_feats(
    const float* __restrict__ X, const float* __restrict__ W,
    const float* __restrict__ a_self, const float* __restrict__ a_neigh) {
    const int ROWS = 16;
    int bi = blockIdx.x;
    int b  = bi >> 7;             // / (2048/16)
    int n0 = (bi & 127) * ROWS;
    int t = threadIdx.x;
    int h = t >> 6, o = t & 63;

    __shared__ float X_s[ROWS * 64];
    __shared__ float ss_s[ROWS * 4], sn_s[ROWS * 4];

    for (int idx = t; idx < ROWS * 64; idx += 256) {
        int r = idx >> 6, f = idx & 63;
        X_s[idx] = X[(size_t)(b * NN + n0 + r) * FF + f];
    }
    if (t < ROWS * 4) { ss_s[t] = 0.f; sn_s[t] = 0.f; }

    // W column for this (h,o) into registers
    float w_reg[64];
#pragma unroll
    for (int f = 0; f < 64; ++f) w_reg[f] = W[(h * 64 + f) * 64 + o];
    float as_v = a_self[h * 64 + o];
    float an_v = a_neigh[h * 64 + o];
    __syncthreads();

    for (int r = 0; r < ROWS; ++r) {
        float acc = 0.f;
#pragma unroll
        for (int f = 0; f < 64; ++f) acc += X_s[r * 64 + f] * w_reg[f];
        g_feats[((size_t)(b * HH + h) * NN + n0 + r) * FH + o] = acc;
        float ps = acc * as_v, pn = acc * an_v;
#pragma unroll
        for (int d = 16; d > 0; d >>= 1) {
            ps += __shfl_xor_sync(0xffffffffu, ps, d);
            pn += __shfl_xor_sync(0xffffffffu, pn, d);
        }
        if ((t & 31) == 0) {
            atomicAdd(&ss_s[r * 4 + h], ps);
            atomicAdd(&sn_s[r * 4 + h], pn);
        }
    }
    __syncthreads();
    if (t < ROWS * 4) {
        int r = t >> 2, hh = t & 3;
        g_ss[(size_t)(b * HH + hh) * NN + n0 + r] = ss_s[t];
        g_sn[(size_t)(b * HH + hh) * NN + n0 + r] = sn_s[t];
    }
}

// ==================== Kernel 2: fused sparse attention ====================
// grid = (N/TI, B) = (32, 8), block = 256 (8 warps).
// Warp w owns 32 tasks: head h = w>>1, rows il = (w&1)*32 .. +31.
// Each lane holds float2 acc per task (outputs o = 2*lane, 2*lane+1).

struct Smem2 {
    float feats[HH * TJ * FH];      // 131072 B  [h][j][o]
    float sn[HH * TJ];              // 2048 B
    float ss[HH * TI];              // 1024 B
    float ssum[HH * TI];            // 1024 B
    unsigned char nbr[TI * TJ];     // 8192 B
    int cnt[TI];                    // 256 B
};

extern __shared__ char smem_raw2[];

__global__ __launch_bounds__(256, 1) void k_attn(
    const float* __restrict__ A, const float* __restrict__ bias,
    float* __restrict__ out) {
    Smem2* S = reinterpret_cast<Smem2*>(smem_raw2);
    const int b  = blockIdx.y;
    const int i0 = blockIdx.x * TI;
    const int t = threadIdx.x, lane = t & 31, w = t >> 5;
    const int h = w >> 1;
    const int ilbase = (w & 1) * 32;

    float2 acc[32];
#pragma unroll
    for (int k = 0; k < 32; ++k) acc[k] = make_float2(0.f, 0.f);

    {   // init ssum, stage s_self for this row tile
        int hh = t >> 6, il = t & 63;
        S->ssum[t] = 0.f;
        S->ss[t]   = g_ss[(size_t)(b * HH + hh) * NN + i0 + il];
    }
    __syncthreads();

#pragma unroll 1
    for (int jt = 0; jt < NN / TJ; ++jt) {
        const int j0 = jt * TJ;

        // ---- stage feats tile: 8192 float4, coalesced ----
        for (int e = t; e < HH * TJ * FH / 4; e += 256) {
            int hh  = e >> 11;          // 2048 float4 per head
            int rem = e & 2047;
            int j   = rem >> 4;         // 16 float4 per row
            int o4  = rem & 15;
            float4 v = *reinterpret_cast<const float4*>(
                &g_feats[((size_t)(b * HH + hh) * NN + j0 + j) * FH + (o4 << 2)]);
            *reinterpret_cast<float4*>(&S->feats[(hh * TJ + j) * FH + (o4 << 2)]) = v;
        }
        // ---- stage s_neigh tile ----
        for (int e = t; e < HH * TJ; e += 256) {
            int hh = e >> 7, j = e & 127;
            S->sn[e] = g_sn[(size_t)(b * HH + hh) * NN + j0 + j];
        }
        // ---- compact A tile: warp w -> rows w*8..w*8+7 ----
        {
            float av[8][4];
            const float* abase = A + ((size_t)(b * NN + i0 + w * 8)) * NN + j0;
#pragma unroll
            for (int rr = 0; rr < 8; ++rr)
#pragma unroll
                for (int c = 0; c < 4; ++c)
                    av[rr][c] = abase[(size_t)rr * NN + c * 32 + lane];
#pragma unroll
            for (int rr = 0; rr < 8; ++rr) {
                int il = w * 8 + rr;
                int cnt = 0;
#pragma unroll
                for (int c = 0; c < 4; ++c) {
                    bool nz = (av[rr][c] != 0.f);
                    unsigned m = __ballot_sync(0xffffffffu, nz);
                    int pos = cnt + __popc(m & ((1u << lane) - 1u));
                    if (nz) S->nbr[il * TJ + pos] = (unsigned char)(c * 32 + lane);
                    cnt += __popc(m);
                }
                if (lane == 0) S->cnt[il] = cnt;
            }
        }
        __syncthreads();

        // ---- accumulate: 32 tasks per warp ----
#pragma unroll
        for (int k = 0; k < 32; ++k) {
            const int il = ilbase + k;
            const int cnt = S->cnt[il];
            const float ssv = S->ss[h * TI + il];
            float2 a2 = acc[k];
            const float* fb = &S->feats[h * TJ * FH];
            for (int s0 = 0; s0 < cnt; s0 += 32) {
                int s = s0 + lane;
                bool valid = (s < cnt);
                int j = valid ? (int)S->nbr[il * TJ + s] : 0;
                float sc = ssv + S->sn[h * TJ + j];
                sc = sc > 0.f ? sc : 0.2f * sc;          // leaky_relu(0.2)
                float p = valid ? __expf(sc) : 0.f;
                float r = p;
#pragma unroll
                for (int d = 16; d > 0; d >>= 1) r += __shfl_xor_sync(0xffffffffu, r, d);
                if (lane == 0) S->ssum[h * TI + il] += r;
                int nlim = min(32, cnt - s0);
                for (int q = 0; q < nlim; ++q) {
                    float pj = __shfl_sync(0xffffffffu, p, q);
                    int  jj  = __shfl_sync(0xffffffffu, j, q);
                    float2 f2 = *reinterpret_cast<const float2*>(&fb[jj * FH + 2 * lane]);
                    a2.x += pj * f2.x;
                    a2.y += pj * f2.y;
                }
            }
            acc[k] = a2;
        }
        __syncthreads();
    }

    // ---- epilogue: normalize, bias, relu, write [b][n][h*64+o] ----
    float2 bv = *reinterpret_cast<const float2*>(&bias[h * FH + 2 * lane]);
#pragma unroll
    for (int k = 0; k < 32; ++k) {
        int il = ilbase + k;
        float inv = 1.f / S->ssum[h * TI + il];
        float ox = fmaxf(acc[k].x * inv + bv.x, 0.f);
        float oy = fmaxf(acc[k].y * inv + bv.y, 0.f);
        *reinterpret_cast<float2*>(
            &out[((size_t)(b * NN + i0 + il)) * (HH * FH) + h * FH + 2 * lane]) =
            make_float2(ox, oy);
    }
}

// ==================== launch ====================
extern "C" void kernel_launch(void* const* d_in, const int* in_sizes, int n_in,
                              void* d_out, int out_size) {
    const float* X       = (const float*)d_in[0];
    const float* A       = (const float*)d_in[1];
    const float* W       = (const float*)d_in[2];
    const float* bias    = (const float*)d_in[3];
    const float* a_self  = (const float*)d_in[4];
    const float* a_neigh = (const float*)d_in[5];
    float* out = (float*)d_out;

    static bool attr_set = false;
    if (!attr_set) {
        cudaFuncSetAttribute(k_attn, cudaFuncAttributeMaxDynamicSharedMemorySize,
                             (int)sizeof(Smem2));
        attr_set = true;
    }

    k_feats<<<BB * NN / 16, 256>>>(X, W, a_self, a_neigh);
    dim3 grid2(NN / TI, BB);
    k_attn<<<grid2, 256, sizeof(Smem2)>>>(A, bias, out);
}

// round 3
// speedup vs baseline: 5.0619x; 5.0619x over previous
#include <cuda_runtime.h>
#include <cuda_fp16.h>
#include <cstdint>
#include <math.h>

// ---------------- problem constants ----------------
#define BB 8
#define NN 2048
#define FF 64
#define FHD 64
#define HH 4

#define TIx 64            // rows per CTA
#define TJx 64            // j per tile
#define NJT (NN / TJx)    // 32 j-tiles
#define THR2 256          // k_attn threads (8 warps)

// ---------------- scratch ----------------
__device__ __half g_feats16[(size_t)BB * HH * NN * FHD]; // [b][h][n][o] fp16
__device__ float  g_ss[BB * HH * NN];
__device__ float  g_sn[BB * HH * NN];

// ---------------- helpers ----------------
__device__ __forceinline__ uint32_t smem_u32(const void* p) {
    uint32_t a;
    asm("{ .reg .u64 t; cvta.to.shared.u64 t, %1; cvt.u32.u64 %0, t; }" : "=r"(a) : "l"(p));
    return a;
}
#define CP_ASYNC16(dst, src) \
    asm volatile("cp.async.cg.shared.global [%0], [%1], 16;" :: "r"(dst), "l"(src) : "memory")
#define CP_COMMIT() asm volatile("cp.async.commit_group;" ::: "memory")
#define CP_WAIT(n)  asm volatile("cp.async.wait_group %0;" :: "n"(n) : "memory")

__device__ __forceinline__ void ldmx4t(uint32_t* r, uint32_t addr) {
    asm volatile("ldmatrix.sync.aligned.m8n8.x4.trans.shared.b16 {%0,%1,%2,%3}, [%4];"
                 : "=r"(r[0]), "=r"(r[1]), "=r"(r[2]), "=r"(r[3]) : "r"(addr));
}
__device__ __forceinline__ void mma16816(float* c, const uint32_t* a, uint32_t b0, uint32_t b1) {
    asm volatile(
        "mma.sync.aligned.m16n8k16.row.col.f32.f16.f16.f32 "
        "{%0,%1,%2,%3},{%4,%5,%6,%7},{%8,%9},{%0,%1,%2,%3};"
        : "+f"(c[0]), "+f"(c[1]), "+f"(c[2]), "+f"(c[3])
        : "r"(a[0]), "r"(a[1]), "r"(a[2]), "r"(a[3]), "r"(b0), "r"(b1));
}
__device__ __forceinline__ float pval(float ssv, float snv, float av) {
    float s = ssv + snv;
    s = fmaxf(s, 0.2f * s);          // leaky_relu slope 0.2
    float e = __expf(s);
    return (av != 0.f) ? e : 0.f;
}

// ---------------- smem layout per buffer (bytes) ----------------
// A: [64][72] f32 (pad 72 -> conflict-free float2 reads, 288B rows, 16B aligned)
// V: [4][64][72] half (144B row pitch -> conflict-free ldmatrix)
// SN: [4][64] f32
#define OFF_A   0
#define OFF_V   18432
#define OFF_SN  55296
#define BUFSZ   56320
#define SMEM_SZ (2 * BUFSZ)   // 112640 B -> 2 CTAs/SM fits 228KB

// ==================== Kernel 1: feats (fp16) + logit dots ====================
__global__ __launch_bounds__(256) void k_feats(
    const float* __restrict__ X, const float* __restrict__ W,
    const float* __restrict__ a_self, const float* __restrict__ a_neigh) {
    const int ROWS = 16;
    int bi = blockIdx.x;
    int b  = bi >> 7;
    int n0 = (bi & 127) * ROWS;
    int t = threadIdx.x;
    int h = t >> 6, o = t & 63;

    __shared__ float X_s[ROWS * 64];
    __shared__ float ss_s[ROWS * 4], sn_s[ROWS * 4];
    __shared__ __half F_s[ROWS][256];

    for (int idx = t; idx < ROWS * 64; idx += 256)
        X_s[idx] = X[(size_t)(b * NN + n0 + (idx >> 6)) * FF + (idx & 63)];
    if (t < ROWS * 4) { ss_s[t] = 0.f; sn_s[t] = 0.f; }

    float w_reg[64];
#pragma unroll
    for (int f = 0; f < 64; ++f) w_reg[f] = W[(h * 64 + f) * 64 + o];
    float as_v = a_self[h * 64 + o];
    float an_v = a_neigh[h * 64 + o];
    __syncthreads();

#pragma unroll
    for (int r = 0; r < ROWS; ++r) {
        float acc = 0.f;
#pragma unroll
        for (int f = 0; f < 64; ++f) acc += X_s[r * 64 + f] * w_reg[f];
        F_s[r][h * 64 + o] = __float2half(acc);
        float ps = acc * as_v, pn = acc * an_v;
#pragma unroll
        for (int d = 16; d > 0; d >>= 1) {
            ps += __shfl_xor_sync(0xffffffffu, ps, d);
            pn += __shfl_xor_sync(0xffffffffu, pn, d);
        }
        if ((t & 31) == 0) {
            atomicAdd(&ss_s[r * 4 + h], ps);
            atomicAdd(&sn_s[r * 4 + h], pn);
        }
    }
    __syncthreads();

    // coalesced fp16 writeout: [b][h][n][o]
#pragma unroll
    for (int k = 0; k < 2; ++k) {
        int e = t + k * 256;              // 512 uint4 total
        int r = e >> 5, c = (e & 31) * 8; // c in halves
        int hh = c >> 6, o0 = c & 63;
        uint4 v = *reinterpret_cast<const uint4*>(&F_s[r][c]);
        *reinterpret_cast<uint4*>(
            &g_feats16[((size_t)(b * HH + hh) * NN + n0 + r) * FHD + o0]) = v;
    }
    if (t < ROWS * 4) {
        int r = t >> 2, hh = t & 3;
        g_ss[(size_t)(b * HH + hh) * NN + n0 + r] = ss_s[t];
        g_sn[(size_t)(b * HH + hh) * NN + n0 + r] = sn_s[t];
    }
}

// ==================== Kernel 2: flash-GAT via mma.sync ====================
extern __shared__ char smem[];

__global__ __launch_bounds__(THR2, 2) void k_attn(
    const float* __restrict__ A, const float* __restrict__ bias,
    float* __restrict__ out) {
    const int b  = blockIdx.y;
    const int i0 = blockIdx.x * TIx;
    const int t = threadIdx.x, lane = t & 31, wid = t >> 5;
    const int h = wid >> 1;            // head
    const int rbase = (wid & 1) * 32;  // local row base (warp owns 32 rows)
    const int g = lane >> 2;           // frag row group 0..7
    const int q = lane & 3;            // frag col group 0..3
    const uint32_t sb = smem_u32(smem);

    // ---- cp.async stager ----
    auto issue_tile = [&](int jt, int buf) {
        const uint32_t base = sb + buf * BUFSZ;
        const int j0 = jt * TJx;
#pragma unroll
        for (int k = 0; k < 4; ++k) {            // A: 64x64 f32
            int e = t + k * 256;
            int r = e >> 4, c4 = e & 15;
            CP_ASYNC16(base + OFF_A + r * 288 + c4 * 16,
                       &A[((size_t)(b * NN + i0 + r)) * NN + j0 + c4 * 4]);
        }
#pragma unroll
        for (int k = 0; k < 8; ++k) {            // V: 4x64x64 half
            int e = t + k * 256;
            int hh = e >> 9, j = (e >> 3) & 63, o8 = e & 7;
            CP_ASYNC16(base + OFF_V + hh * 9216 + j * 144 + o8 * 16,
                       &g_feats16[((size_t)(b * HH + hh) * NN + j0 + j) * FHD + o8 * 8]);
        }
        if (t < 64) {                            // sn: 4x64 f32
            CP_ASYNC16(base + OFF_SN + t * 16,
                       &g_sn[(size_t)(b * HH + (t >> 4)) * NN + j0 + (t & 15) * 4]);
        }
        CP_COMMIT();
    };

    // ---- per-thread s_self values (4 rows: m in {0,1}, lo/hi) ----
    float ssr[2][2];
#pragma unroll
    for (int m = 0; m < 2; ++m)
#pragma unroll
        for (int hi = 0; hi < 2; ++hi)
            ssr[m][hi] = g_ss[(size_t)(b * HH + h) * NN + i0 + rbase + m * 16 + g + hi * 8];

    float acc[2][8][4];
#pragma unroll
    for (int m = 0; m < 2; ++m)
#pragma unroll
        for (int n = 0; n < 8; ++n)
#pragma unroll
            for (int c = 0; c < 4; ++c) acc[m][n][c] = 0.f;

    float rsum[2][2] = {{0.f, 0.f}, {0.f, 0.f}};

    issue_tile(0, 0);

#pragma unroll 1
    for (int jt = 0; jt < NJT; ++jt) {
        const int buf = jt & 1;
        if (jt + 1 < NJT) { issue_tile(jt + 1, buf ^ 1); CP_WAIT(1); }
        else             { CP_WAIT(0); }
        __syncthreads();

        const float* As  = (const float*)(smem + buf * BUFSZ + OFF_A);
        const float* snh = (const float*)(smem + buf * BUFSZ + OFF_SN) + h * 64;
        const uint32_t sbVh = sb + buf * BUFSZ + OFF_V + h * 9216;

        // ---- build P directly in mma A-frag layout ----
        uint32_t afr[2][4][4];
#pragma unroll
        for (int k = 0; k < 4; ++k) {
            const int jc = k * 16 + q * 2;
            float2 sn0 = *(const float2*)(snh + jc);
            float2 sn8 = *(const float2*)(snh + jc + 8);
#pragma unroll
            for (int m = 0; m < 2; ++m) {
                const int rlo = rbase + m * 16 + g;
                float2 alo0 = *(const float2*)(As + rlo * 72 + jc);
                float2 ahi0 = *(const float2*)(As + (rlo + 8) * 72 + jc);
                float2 alo8 = *(const float2*)(As + rlo * 72 + jc + 8);
                float2 ahi8 = *(const float2*)(As + (rlo + 8) * 72 + jc + 8);
                float sl = ssr[m][0], sh = ssr[m][1];

                __half2 h0 = __floats2half2_rn(pval(sl, sn0.x, alo0.x), pval(sl, sn0.y, alo0.y));
                __half2 h1 = __floats2half2_rn(pval(sh, sn0.x, ahi0.x), pval(sh, sn0.y, ahi0.y));
                __half2 h2v = __floats2half2_rn(pval(sl, sn8.x, alo8.x), pval(sl, sn8.y, alo8.y));
                __half2 h3 = __floats2half2_rn(pval(sh, sn8.x, ahi8.x), pval(sh, sn8.y, ahi8.y));

                afr[m][k][0] = *reinterpret_cast<uint32_t*>(&h0);
                afr[m][k][1] = *reinterpret_cast<uint32_t*>(&h1);
                afr[m][k][2] = *reinterpret_cast<uint32_t*>(&h2v);
                afr[m][k][3] = *reinterpret_cast<uint32_t*>(&h3);

                // denominator from the SAME half-rounded p (error correlation)
                float2 f0 = __half22float2(h0), f1 = __half22float2(h1);
                float2 f2 = __half22float2(h2v), f3 = __half22float2(h3);
                rsum[m][0] += (f0.x + f0.y) + (f2.x + f2.y);
                rsum[m][1] += (f1.x + f1.y) + (f3.x + f3.y);
            }
        }

        // ---- P @ V via HMMA ----
        const int rowlane = lane & 15, colsel = lane >> 4;
#pragma unroll
        for (int n = 0; n < 4; ++n) {       // n16 blocks
#pragma unroll
            for (int k = 0; k < 4; ++k) {   // k16 steps
                uint32_t bfr[4];
                ldmx4t(bfr, sbVh + (k * 16 + rowlane) * 144 + (n * 16 + colsel * 8) * 2);
#pragma unroll
                for (int m = 0; m < 2; ++m) {
                    mma16816(acc[m][2 * n],     afr[m][k], bfr[0], bfr[1]);
                    mma16816(acc[m][2 * n + 1], afr[m][k], bfr[2], bfr[3]);
                }
            }
        }
        __syncthreads();
    }

    // ---- reduce row sums across the 4 lanes sharing a row ----
    float inv[2][2];
#pragma unroll
    for (int m = 0; m < 2; ++m)
#pragma unroll
        for (int hi = 0; hi < 2; ++hi) {
            float r = rsum[m][hi];
            r += __shfl_xor_sync(0xffffffffu, r, 1);
            r += __shfl_xor_sync(0xffffffffu, r, 2);
            inv[m][hi] = 1.f / r;
        }

    // ---- epilogue: normalize + bias + relu, direct float2 stores ----
#pragma unroll
    for (int n = 0; n < 8; ++n) {
        const int col = h * 64 + n * 8 + q * 2;
        float2 bv = *reinterpret_cast<const float2*>(&bias[col]);
#pragma unroll
        for (int m = 0; m < 2; ++m) {
            const int rlo = i0 + rbase + m * 16 + g;
            float2 lo, hi2;
            lo.x  = fmaxf(acc[m][n][0] * inv[m][0] + bv.x, 0.f);
            lo.y  = fmaxf(acc[m][n][1] * inv[m][0] + bv.y, 0.f);
            hi2.x = fmaxf(acc[m][n][2] * inv[m][1] + bv.x, 0.f);
            hi2.y = fmaxf(acc[m][n][3] * inv[m][1] + bv.y, 0.f);
            *reinterpret_cast<float2*>(&out[((size_t)(b * NN + rlo)) * 256 + col]) = lo;
            *reinterpret_cast<float2*>(&out[((size_t)(b * NN + rlo + 8)) * 256 + col]) = hi2;
        }
    }
}

// ==================== launch ====================
extern "C" void kernel_launch(void* const* d_in, const int* in_sizes, int n_in,
                              void* d_out, int out_size) {
    const float* X       = (const float*)d_in[0];
    const float* A       = (const float*)d_in[1];
    const float* W       = (const float*)d_in[2];
    const float* bias    = (const float*)d_in[3];
    const float* a_self  = (const float*)d_in[4];
    const float* a_neigh = (const float*)d_in[5];
    float* out = (float*)d_out;

    static bool attr_set = false;
    if (!attr_set) {
        cudaFuncSetAttribute(k_attn, cudaFuncAttributeMaxDynamicSharedMemorySize, SMEM_SZ);
        attr_set = true;
    }

    k_feats<<<BB * NN / 16, 256>>>(X, W, a_self, a_neigh);
    dim3 grid2(NN / TIx, BB);
    k_attn<<<grid2, THR2, SMEM_SZ>>>(A, bias, out);
}

// round 4
// speedup vs baseline: 5.3323x; 1.0534x over previous
#include <cuda_runtime.h>
#include <cuda_fp16.h>
#include <cstdint>
#include <math.h>

// ---------------- problem constants ----------------
#define BB 8
#define NN 2048
#define FF 64
#define FHD 64
#define HH 4

#define TIx 64            // rows per CTA
#define TJx 64            // j per tile
#define NJT (NN / TJx)    // 32 j-tiles
#define THR2 256          // k_attn threads (8 warps)

// ---------------- scratch ----------------
__device__ __half g_feats16[(size_t)BB * HH * NN * FHD]; // [b][h][n][o] fp16
__device__ float2 g_EG[BB * HH * NN];  // (exp(ss), exp(0.2 ss))
__device__ float2 g_FH[BB * HH * NN];  // (exp(sn), exp(0.2 sn))
__device__ float  g_wa[2 * HH * FF];   // [which][h][f] = sum_o W[h][f][o]*a[h][o]

// ---------------- helpers ----------------
__device__ __forceinline__ uint32_t smem_u32(const void* p) {
    uint32_t a;
    asm("{ .reg .u64 t; cvta.to.shared.u64 t, %1; cvt.u32.u64 %0, t; }" : "=r"(a) : "l"(p));
    return a;
}
#define CP_ASYNC16(dst, src) \
    asm volatile("cp.async.cg.shared.global [%0], [%1], 16;" :: "r"(dst), "l"(src) : "memory")
#define CP_COMMIT() asm volatile("cp.async.commit_group;" ::: "memory")
#define CP_WAIT(n)  asm volatile("cp.async.wait_group %0;" :: "n"(n) : "memory")

__device__ __forceinline__ void ldmx4t(uint32_t* r, uint32_t addr) {
    asm volatile("ldmatrix.sync.aligned.m8n8.x4.trans.shared.b16 {%0,%1,%2,%3}, [%4];"
                 : "=r"(r[0]), "=r"(r[1]), "=r"(r[2]), "=r"(r[3]) : "r"(addr));
}
__device__ __forceinline__ void mma16816(float* c, const uint32_t* a, uint32_t b0, uint32_t b1) {
    asm volatile(
        "mma.sync.aligned.m16n8k16.row.col.f32.f16.f16.f32 "
        "{%0,%1,%2,%3},{%4,%5,%6,%7},{%8,%9},{%0,%1,%2,%3};"
        : "+f"(c[0]), "+f"(c[1]), "+f"(c[2]), "+f"(c[3])
        : "r"(a[0]), "r"(a[1]), "r"(a[2]), "r"(a[3]), "r"(b0), "r"(b1));
}

// ---------------- smem layout per buffer (bytes) ----------------
// A: [64][72] f32 (pad 72 -> conflict-free), V: [4][64][72] half (144B pitch), FH: [4][64] float2
#define OFF_A   0
#define OFF_V   18432
#define OFF_FH  55296
#define BUFSZ   57344
#define SMEM_SZ (2 * BUFSZ)   // 114688 B -> 2 CTAs/SM

// ==================== Kernel 0: wa = W . a ====================
__global__ __launch_bounds__(512) void k_prep(
    const float* __restrict__ W, const float* __restrict__ a_self,
    const float* __restrict__ a_neigh) {
    int t = threadIdx.x;
    int which = t >> 8, hf = t & 255, h = hf >> 6;
    const float* ap = (which ? a_neigh : a_self) + h * 64;
    const float* wrow = W + (size_t)hf * 64;
    float s = 0.f;
#pragma unroll
    for (int o = 0; o < 64; ++o) s += wrow[o] * ap[o];
    g_wa[t] = s;
}

// ==================== Kernel 1: feats (fp16) + E/G/F/H ====================
__global__ __launch_bounds__(256) void k_feats(
    const float* __restrict__ X, const float* __restrict__ W) {
    const int ROWS = 16;
    int bi = blockIdx.x;
    int b  = bi >> 7;
    int n0 = (bi & 127) * ROWS;
    int t = threadIdx.x;
    int h = t >> 6, o = t & 63;

    __shared__ float X_s[ROWS * 64];
    __shared__ __half F_s[ROWS][256];

    for (int idx = t; idx < ROWS * 64; idx += 256)
        X_s[idx] = X[(size_t)(b * NN + n0 + (idx >> 6)) * FF + (idx & 63)];

    float w_reg[64];
#pragma unroll
    for (int f = 0; f < 64; ++f) w_reg[f] = W[(h * 64 + f) * 64 + o];
    __syncthreads();

#pragma unroll
    for (int r = 0; r < ROWS; ++r) {
        float acc = 0.f;
#pragma unroll
        for (int f = 0; f < 64; ++f) acc += X_s[r * 64 + f] * w_reg[f];
        F_s[r][h * 64 + o] = __float2half(acc);
    }

    // ss/sn via precomputed wa, then exp pairs
    if (t < 128) {
        int r = t >> 3, hh = (t >> 1) & 3, wh = t & 1;
        const float* wap = g_wa + wh * 256 + hh * 64;
        float s = 0.f;
#pragma unroll
        for (int f = 0; f < 64; ++f) s += X_s[r * 64 + f] * wap[f];
        float2 eg = make_float2(__expf(s), __expf(0.2f * s));
        (wh ? g_FH : g_EG)[(size_t)(b * HH + hh) * NN + n0 + r] = eg;
    }
    __syncthreads();

    // coalesced fp16 writeout: [b][h][n][o]
#pragma unroll
    for (int k = 0; k < 2; ++k) {
        int e = t + k * 256;
        int r = e >> 5, c = (e & 31) * 8;
        int hh = c >> 6, o0 = c & 63;
        uint4 v = *reinterpret_cast<const uint4*>(&F_s[r][c]);
        *reinterpret_cast<uint4*>(
            &g_feats16[((size_t)(b * HH + hh) * NN + n0 + r) * FHD + o0]) = v;
    }
}

// ==================== Kernel 2: flash-GAT via mma.sync ====================
extern __shared__ char smem[];

__global__ __launch_bounds__(THR2, 2) void k_attn(
    const float* __restrict__ A, const float* __restrict__ bias,
    float* __restrict__ out) {
    const int b  = blockIdx.y;
    const int i0 = blockIdx.x * TIx;
    const int t = threadIdx.x, lane = t & 31, wid = t >> 5;
    const int h = wid >> 1;            // head
    const int rbase = (wid & 1) * 32;  // warp owns 32 rows
    const int g = lane >> 2;           // frag row group 0..7
    const int q = lane & 3;            // frag col group 0..3
    const uint32_t sb = smem_u32(smem);

    auto issue_tile = [&](int jt, int buf) {
        const uint32_t base = sb + buf * BUFSZ;
        const int j0 = jt * TJx;
#pragma unroll
        for (int k = 0; k < 4; ++k) {            // A: 64x64 f32
            int e = t + k * 256;
            int r = e >> 4, c4 = e & 15;
            CP_ASYNC16(base + OFF_A + r * 288 + c4 * 16,
                       &A[((size_t)(b * NN + i0 + r)) * NN + j0 + c4 * 4]);
        }
#pragma unroll
        for (int k = 0; k < 8; ++k) {            // V: 4x64x64 half
            int e = t + k * 256;
            int hh = e >> 9, j = (e >> 3) & 63, o8 = e & 7;
            CP_ASYNC16(base + OFF_V + hh * 9216 + j * 144 + o8 * 16,
                       &g_feats16[((size_t)(b * HH + hh) * NN + j0 + j) * FHD + o8 * 8]);
        }
        if (t < 128) {                           // FH: 4x64 float2
            int hh = t >> 5, jj = (t & 31) * 2;
            CP_ASYNC16(base + OFF_FH + hh * 512 + jj * 8,
                       &g_FH[(size_t)(b * HH + hh) * NN + j0 + jj]);
        }
        CP_COMMIT();
    };

    // per-thread row constants: E, G for 4 rows (m in {0,1} x lo/hi)
    float Er[2][2], Gr[2][2];
#pragma unroll
    for (int m = 0; m < 2; ++m)
#pragma unroll
        for (int hi = 0; hi < 2; ++hi) {
            float2 eg = g_EG[(size_t)(b * HH + h) * NN + i0 + rbase + m * 16 + g + hi * 8];
            Er[m][hi] = eg.x;
            Gr[m][hi] = eg.y;
        }

    float acc[2][8][4];
#pragma unroll
    for (int m = 0; m < 2; ++m)
#pragma unroll
        for (int n = 0; n < 8; ++n)
#pragma unroll
            for (int c = 0; c < 4; ++c) acc[m][n][c] = 0.f;

    float rsum[2][2] = {{0.f, 0.f}, {0.f, 0.f}};

    issue_tile(0, 0);

#pragma unroll 1
    for (int jt = 0; jt < NJT; ++jt) {
        const int buf = jt & 1;
        if (jt + 1 < NJT) { issue_tile(jt + 1, buf ^ 1); CP_WAIT(1); }
        else             { CP_WAIT(0); }
        __syncthreads();

        const float* As = (const float*)(smem + buf * BUFSZ + OFF_A);
        const float2* FHh = (const float2*)(smem + buf * BUFSZ + OFF_FH) + h * 64;
        const uint32_t sbVh = sb + buf * BUFSZ + OFF_V + h * 9216;

        // ---- build P in mma A-frag layout: p = max(E*F, G*H) * A ----
        uint32_t afr[2][4][4];
#pragma unroll
        for (int k = 0; k < 4; ++k) {
            const int jc = k * 16 + q * 2;
            float2 fh0 = FHh[jc], fh1 = FHh[jc + 1];
            float2 fh8 = FHh[jc + 8], fh9 = FHh[jc + 9];
#pragma unroll
            for (int m = 0; m < 2; ++m) {
                const int rlo = rbase + m * 16 + g;
                float2 alo0 = *(const float2*)(As + rlo * 72 + jc);
                float2 ahi0 = *(const float2*)(As + (rlo + 8) * 72 + jc);
                float2 alo8 = *(const float2*)(As + rlo * 72 + jc + 8);
                float2 ahi8 = *(const float2*)(As + (rlo + 8) * 72 + jc + 8);
                float El = Er[m][0], Gl = Gr[m][0], Eh = Er[m][1], Gh = Gr[m][1];

                float p00 = fmaxf(El * fh0.x, Gl * fh0.y) * alo0.x;
                float p01 = fmaxf(El * fh1.x, Gl * fh1.y) * alo0.y;
                float p10 = fmaxf(Eh * fh0.x, Gh * fh0.y) * ahi0.x;
                float p11 = fmaxf(Eh * fh1.x, Gh * fh1.y) * ahi0.y;
                float p08 = fmaxf(El * fh8.x, Gl * fh8.y) * alo8.x;
                float p09 = fmaxf(El * fh9.x, Gl * fh9.y) * alo8.y;
                float p18 = fmaxf(Eh * fh8.x, Gh * fh8.y) * ahi8.x;
                float p19 = fmaxf(Eh * fh9.x, Gh * fh9.y) * ahi8.y;

                rsum[m][0] += (p00 + p01) + (p08 + p09);
                rsum[m][1] += (p10 + p11) + (p18 + p19);

                __half2 h0 = __floats2half2_rn(p00, p01);
                __half2 h1 = __floats2half2_rn(p10, p11);
                __half2 h2v = __floats2half2_rn(p08, p09);
                __half2 h3 = __floats2half2_rn(p18, p19);
                afr[m][k][0] = *reinterpret_cast<uint32_t*>(&h0);
                afr[m][k][1] = *reinterpret_cast<uint32_t*>(&h1);
                afr[m][k][2] = *reinterpret_cast<uint32_t*>(&h2v);
                afr[m][k][3] = *reinterpret_cast<uint32_t*>(&h3);
            }
        }

        // ---- P @ V via HMMA ----
        const int rowlane = lane & 15, colsel = lane >> 4;
#pragma unroll
        for (int n = 0; n < 4; ++n) {
#pragma unroll
            for (int k = 0; k < 4; ++k) {
                uint32_t bfr[4];
                ldmx4t(bfr, sbVh + (k * 16 + rowlane) * 144 + (n * 16 + colsel * 8) * 2);
#pragma unroll
                for (int m = 0; m < 2; ++m) {
                    mma16816(acc[m][2 * n],     afr[m][k], bfr[0], bfr[1]);
                    mma16816(acc[m][2 * n + 1], afr[m][k], bfr[2], bfr[3]);
                }
            }
        }
        __syncthreads();
    }

    // ---- reduce row sums across the 4 lanes sharing a row ----
    float inv[2][2];
#pragma unroll
    for (int m = 0; m < 2; ++m)
#pragma unroll
        for (int hi = 0; hi < 2; ++hi) {
            float r = rsum[m][hi];
            r += __shfl_xor_sync(0xffffffffu, r, 1);
            r += __shfl_xor_sync(0xffffffffu, r, 2);
            inv[m][hi] = 1.f / r;
        }

    // ---- epilogue: normalize + bias + relu ----
#pragma unroll
    for (int n = 0; n < 8; ++n) {
        const int col = h * 64 + n * 8 + q * 2;
        float2 bv = *reinterpret_cast<const float2*>(&bias[col]);
#pragma unroll
        for (int m = 0; m < 2; ++m) {
            const int rlo = i0 + rbase + m * 16 + g;
            float2 lo, hi2;
            lo.x  = fmaxf(acc[m][n][0] * inv[m][0] + bv.x, 0.f);
            lo.y  = fmaxf(acc[m][n][1] * inv[m][0] + bv.y, 0.f);
            hi2.x = fmaxf(acc[m][n][2] * inv[m][1] + bv.x, 0.f);
            hi2.y = fmaxf(acc[m][n][3] * inv[m][1] + bv.y, 0.f);
            *reinterpret_cast<float2*>(&out[((size_t)(b * NN + rlo)) * 256 + col]) = lo;
            *reinterpret_cast<float2*>(&out[((size_t)(b * NN + rlo + 8)) * 256 + col]) = hi2;
        }
    }
}

// ==================== launch ====================
extern "C" void kernel_launch(void* const* d_in, const int* in_sizes, int n_in,
                              void* d_out, int out_size) {
    const float* X       = (const float*)d_in[0];
    const float* A       = (const float*)d_in[1];
    const float* W       = (const float*)d_in[2];
    const float* bias    = (const float*)d_in[3];
    const float* a_self  = (const float*)d_in[4];
    const float* a_neigh = (const float*)d_in[5];
    float* out = (float*)d_out;

    static bool attr_set = false;
    if (!attr_set) {
        cudaFuncSetAttribute(k_attn, cudaFuncAttributeMaxDynamicSharedMemorySize, SMEM_SZ);
        attr_set = true;
    }

    k_prep<<<1, 512>>>(W, a_self, a_neigh);
    k_feats<<<BB * NN / 16, 256>>>(X, W);
    dim3 grid2(NN / TIx, BB);
    k_attn<<<grid2, THR2, SMEM_SZ>>>(A, bias, out);
}